// round 17
// baseline (speedup 1.0000x reference)
#include <cuda_runtime.h>
#include <cuda_bf16.h>
#include <math.h>
#include <stdint.h>

#define K_COMP 64
#define DDIM   256
#define MU_PAD 264     // bf16/row: 132 words -> ldmatrix rows cover all 32 banks

__device__ float g_kappa[K_COMP];   // kappa / ||mu||  (norm folded)
__device__ float g_logC[K_COMP];
__device__ float g_la[K_COMP];
__device__ float g_C2[K_COMP];

// ---------------- prep: constants only (no mu staging); norm folded into kappa' -------
__global__ void prep_fast(const float* __restrict__ alpha_logit,
                          const float* __restrict__ mu_unnorm,
                          const float* __restrict__ log_kappa) {
    __shared__ float sred[4];
    int k = blockIdx.x;
    int tid = threadIdx.x, lane = tid & 31, w = tid >> 5;
    const float s = 0.5f * (float)DDIM - 1.0f;   // 127

    // ||mu_k|| from fp32 source
    float2 v = reinterpret_cast<const float2*>(mu_unnorm + (size_t)k * DDIM)[tid];
    float ss = v.x * v.x + v.y * v.y;
#pragma unroll
    for (int o = 16; o; o >>= 1) ss += __shfl_xor_sync(0xffffffffu, ss, o);
    if (lane == 0) sred[w] = ss;
    __syncthreads();
    float nrm = fmaxf(sqrtf(sred[0] + sred[1] + sred[2] + sred[3]), 1e-12f);

    if (w == 0) {
        float a0 = alpha_logit[lane], a1 = alpha_logit[lane + 32];
        float am = fmaxf(a0, a1);
#pragma unroll
        for (int o = 16; o; o >>= 1) am = fmaxf(am, __shfl_xor_sync(0xffffffffu, am, o));
        float ae = expf(a0 - am) + expf(a1 - am);
#pragma unroll
        for (int o = 16; o; o >>= 1) ae += __shfl_xor_sync(0xffffffffu, ae, o);
        float lse = am + logf(ae);

        float kap = expf(log_kappa[k]) + 1e-6f;
        float lk2 = logf(0.5f * kap);
        float cm0 = lgammaf((float)lane + 1.0f)  + lgammaf((float)lane + s + 1.0f);
        float cm1 = lgammaf((float)lane + 33.0f) + lgammaf((float)lane + s + 33.0f);
        float t0 = fmaf(2.0f * lane + s,        lk2, -cm0);
        float t1 = fmaf(2.0f * (lane + 32) + s, lk2, -cm1);
        float tm = fmaxf(t0, t1);
#pragma unroll
        for (int o = 16; o; o >>= 1) tm = fmaxf(tm, __shfl_xor_sync(0xffffffffu, tm, o));
        float ts = expf(t0 - tm) + expf(t1 - tm);
#pragma unroll
        for (int o = 16; o; o >>= 1) ts += __shfl_xor_sync(0xffffffffu, ts, o);

        if (lane == 0) {
            float lbi  = tm + logf(ts);
            float logC = (float)DDIM * (-0.91893853320467274f) + s * logf(kap) - lbi;
            float la   = alpha_logit[k] - lse;
            g_kappa[k] = kap / nrm;     // fold 1/||mu|| into the dot multiplier
            g_logC[k]  = logC;
            g_la[k]    = la;
            g_C2[k]    = logC + la;
        }
    }
    __syncthreads();   // all writes done before trigger
    cudaTriggerProgrammaticLaunchCompletion();
}

// ---------------- fast exp: FFMA-only ----------------
__device__ __forceinline__ float fexp(float x) {
    x = fmaxf(x, -87.0f);
    float z = x * 1.4426950408889634f;
    float t = z + 12582912.0f;
    float fi = t - 12582912.0f;
    float f = z - fi;
    int  i  = __float_as_int(t) - 0x4B400000;
    float p = 1.3333558e-3f;
    p = fmaf(p, f, 9.6181291e-3f);
    p = fmaf(p, f, 5.5504109e-2f);
    p = fmaf(p, f, 2.4022651e-1f);
    p = fmaf(p, f, 6.9314718e-1f);
    p = fmaf(p, f, 1.0f);
    return __int_as_float(__float_as_int(p) + (i << 23));
}

__device__ __forceinline__ uint32_t f22bf(float2 v) {
    __nv_bfloat162 b = __float22bfloat162_rn(v);
    return *reinterpret_cast<uint32_t*>(&b);
}

// ---------------- main: R10 loop on RAW mu; PDL sync deferred to the epilogue ---------
// smu staging reads mu_unnorm directly (raw bf16, permuted) — prep-independent.
// The ONLY prep-dependent reads (epilogue constants) happen after the mainloop, so
// cudaGridDependencySynchronize sits behind ~60us of GEMM: prep is fully hidden.
__global__ void __launch_bounds__(256, 2)
vmf_main(const float* __restrict__ x,
         const float* __restrict__ mu_unnorm,
         float* __restrict__ out_llh,
         float* __restrict__ out_lp,
         int N) {
    __shared__ __align__(16) __nv_bfloat16 smu[K_COMP][MU_PAD];
    __shared__ float s_kappa[K_COMP], s_logC[K_COMP], s_la[K_COMP], s_C2[K_COMP];

    int tid = threadIdx.x;
    int warp = tid >> 5, lane = tid & 31;
    int row0 = blockIdx.x * 256 + warp * 32;   // 32 rows per warp
    int r  = lane >> 2;        // 0..7
    int cq = (lane & 3) * 2;   // logical col-pair base (epilogue)

    const float* p0 = x + (size_t)(row0 + r) * DDIM + (lane & 3) * 4;

    // ---- prime the x prefetch pipeline (prep-independent) ----
    float4 buf[2][4];
#pragma unroll
    for (int c = 0; c < 2; c++)
#pragma unroll
        for (int g = 0; g < 4; g++)
            buf[c][g] = __ldcs(reinterpret_cast<const float4*>(p0 + c * 16 + g * 8 * DDIM));

    // ---- stage RAW mu with k-pair permutation (prep-independent) ----
    const float2* gmu2 = reinterpret_cast<const float2*>(mu_unnorm);
    for (int idx = tid; idx < K_COMP * (DDIM / 2); idx += 256) {
        int kk = idx >> 7;
        int dp = idx & 127;
        int i  = dp & 7;
        int srcp = (i < 4) ? (2 * i) : (2 * i - 7);
        int src  = (dp & ~7) | srcp;
        float2 v = gmu2[kk * 128 + src];
        reinterpret_cast<__nv_bfloat162*>(&smu[kk][0])[dp] = __float22bfloat162_rn(v);
    }

    uint32_t smu_base = (uint32_t)__cvta_generic_to_shared(&smu[0][0]);
    int li   = lane & 7;
    int csel = (lane >> 3) & 1;
    int tsel = (lane >> 4) & 1;
    uint32_t lm_base = smu_base + (uint32_t)(((li + tsel * 8) * MU_PAD + csel * 8) * 2);

    float acc0[8][4], acc1[8][4];
#pragma unroll
    for (int t = 0; t < 8; t++)
#pragma unroll
        for (int j = 0; j < 4; j++) { acc0[t][j] = 0.0f; acc1[t][j] = 0.0f; }

    __syncthreads();   // smu visible to all warps (NOT a prep dependency)

#pragma unroll
    for (int kk = 0; kk < 16; kk++) {
        int b = kk & 1;
        float4 A0 = buf[b][0], A1 = buf[b][1], A2 = buf[b][2], A3 = buf[b][3];

        uint32_t u0 = f22bf(make_float2(A0.x, A0.y));
        uint32_t u1 = f22bf(make_float2(A1.x, A1.y));
        uint32_t u2 = f22bf(make_float2(A0.z, A0.w));
        uint32_t u3 = f22bf(make_float2(A1.z, A1.w));
        uint32_t v0 = f22bf(make_float2(A2.x, A2.y));
        uint32_t v1 = f22bf(make_float2(A3.x, A3.y));
        uint32_t v2 = f22bf(make_float2(A2.z, A2.w));
        uint32_t v3 = f22bf(make_float2(A3.z, A3.w));

        if (kk < 14) {
            int off = (kk + 2) * 16;
#pragma unroll
            for (int g = 0; g < 4; g++)
                buf[b][g] = __ldcs(reinterpret_cast<const float4*>(p0 + off + g * 8 * DDIM));
        }

        uint32_t lmaddr = lm_base + (uint32_t)(kk * 32);
#pragma unroll
        for (int tp = 0; tp < 4; tp++) {
            uint32_t b0, b1, b2, b3;
            asm volatile(
                "ldmatrix.sync.aligned.m8n8.x4.shared.b16 {%0,%1,%2,%3}, [%4];\n"
                : "=r"(b0), "=r"(b1), "=r"(b2), "=r"(b3)
                : "r"(lmaddr + (uint32_t)(tp * 16 * MU_PAD * 2)));
            asm volatile(
                "mma.sync.aligned.m16n8k16.row.col.f32.bf16.bf16.f32 "
                "{%0,%1,%2,%3}, {%4,%5,%6,%7}, {%8,%9}, {%0,%1,%2,%3};\n"
                : "+f"(acc0[tp*2][0]), "+f"(acc0[tp*2][1]), "+f"(acc0[tp*2][2]), "+f"(acc0[tp*2][3])
                : "r"(u0), "r"(u1), "r"(u2), "r"(u3), "r"(b0), "r"(b1));
            asm volatile(
                "mma.sync.aligned.m16n8k16.row.col.f32.bf16.bf16.f32 "
                "{%0,%1,%2,%3}, {%4,%5,%6,%7}, {%8,%9}, {%0,%1,%2,%3};\n"
                : "+f"(acc0[tp*2+1][0]), "+f"(acc0[tp*2+1][1]), "+f"(acc0[tp*2+1][2]), "+f"(acc0[tp*2+1][3])
                : "r"(u0), "r"(u1), "r"(u2), "r"(u3), "r"(b2), "r"(b3));
            asm volatile(
                "mma.sync.aligned.m16n8k16.row.col.f32.bf16.bf16.f32 "
                "{%0,%1,%2,%3}, {%4,%5,%6,%7}, {%8,%9}, {%0,%1,%2,%3};\n"
                : "+f"(acc1[tp*2][0]), "+f"(acc1[tp*2][1]), "+f"(acc1[tp*2][2]), "+f"(acc1[tp*2][3])
                : "r"(v0), "r"(v1), "r"(v2), "r"(v3), "r"(b0), "r"(b1));
            asm volatile(
                "mma.sync.aligned.m16n8k16.row.col.f32.bf16.bf16.f32 "
                "{%0,%1,%2,%3}, {%4,%5,%6,%7}, {%8,%9}, {%0,%1,%2,%3};\n"
                : "+f"(acc1[tp*2+1][0]), "+f"(acc1[tp*2+1][1]), "+f"(acc1[tp*2+1][2]), "+f"(acc1[tp*2+1][3])
                : "r"(v0), "r"(v1), "r"(v2), "r"(v3), "r"(b2), "r"(b3));
        }
    }

    // ---- NOW wait for prep (overlapped with the entire mainloop above) ----
    cudaGridDependencySynchronize();
    if (tid < K_COMP) {
        s_kappa[tid] = g_kappa[tid];   // kappa' = kappa/||mu||
        s_logC[tid]  = g_logC[tid];
        s_la[tid]    = g_la[tid];
        s_C2[tid]    = g_C2[tid];
    }
    __syncthreads();

    // ---- epilogue: two row-groups, R4 form each ----
#pragma unroll
    for (int G = 0; G < 2; G++) {
        int gr0 = row0 + G * 16 + r, gr1 = gr0 + 8;
        float2* lp0 = reinterpret_cast<float2*>(out_lp + (size_t)gr0 * K_COMP);
        float2* lp1 = reinterpret_cast<float2*>(out_lp + (size_t)gr1 * K_COMP);

        float m0 = -1e30f, m1 = -1e30f;
#pragma unroll
        for (int t = 0; t < 8; t++) {
            int cc = t * 8 + cq;
            float a0 = G ? acc1[t][0] : acc0[t][0];
            float a1 = G ? acc1[t][1] : acc0[t][1];
            float a2 = G ? acc1[t][2] : acc0[t][2];
            float a3 = G ? acc1[t][3] : acc0[t][3];
            float k0 = s_kappa[cc], k1 = s_kappa[cc + 1];
            float lc0 = s_logC[cc], lc1 = s_logC[cc + 1];
            float la0 = s_la[cc],   la1 = s_la[cc + 1];
            float lp00 = fmaf(k0, a0, lc0);
            float lp01 = fmaf(k1, a1, lc1);
            float lp10 = fmaf(k0, a2, lc0);
            float lp11 = fmaf(k1, a3, lc1);
            __stcs(lp0 + (cc >> 1), make_float2(lp00, lp01));
            __stcs(lp1 + (cc >> 1), make_float2(lp10, lp11));
            m0 = fmaxf(m0, fmaxf(lp00 + la0, lp01 + la1));
            m1 = fmaxf(m1, fmaxf(lp10 + la0, lp11 + la1));
        }
        m0 = fmaxf(m0, __shfl_xor_sync(0xffffffffu, m0, 1));
        m0 = fmaxf(m0, __shfl_xor_sync(0xffffffffu, m0, 2));
        m1 = fmaxf(m1, __shfl_xor_sync(0xffffffffu, m1, 1));
        m1 = fmaxf(m1, __shfl_xor_sync(0xffffffffu, m1, 2));

        float s0 = 0.0f, s1 = 0.0f;
#pragma unroll
        for (int t = 0; t < 8; t++) {
            int cc = t * 8 + cq;
            float a0 = G ? acc1[t][0] : acc0[t][0];
            float a1 = G ? acc1[t][1] : acc0[t][1];
            float a2 = G ? acc1[t][2] : acc0[t][2];
            float a3 = G ? acc1[t][3] : acc0[t][3];
            float k0 = s_kappa[cc], k1 = s_kappa[cc + 1];
            float c20 = s_C2[cc],   c21 = s_C2[cc + 1];
            s0 += fexp(fmaf(k0, a0, c20) - m0);
            s0 += fexp(fmaf(k1, a1, c21) - m0);
            s1 += fexp(fmaf(k0, a2, c20) - m1);
            s1 += fexp(fmaf(k1, a3, c21) - m1);
        }
        s0 += __shfl_xor_sync(0xffffffffu, s0, 1);
        s0 += __shfl_xor_sync(0xffffffffu, s0, 2);
        s1 += __shfl_xor_sync(0xffffffffu, s1, 1);
        s1 += __shfl_xor_sync(0xffffffffu, s1, 2);

        if ((lane & 3) == 0) {
            out_llh[gr0] = m0 + __logf(s0);
            out_llh[gr1] = m1 + __logf(s1);
        }
    }
}

// ---------------- launch: prep -> main with programmatic dependent launch -------------
extern "C" void kernel_launch(void* const* d_in, const int* in_sizes, int n_in,
                              void* d_out, int out_size) {
    const float* x           = (const float*)d_in[0];
    const float* alpha_logit = (const float*)d_in[1];
    const float* mu_unnorm   = (const float*)d_in[2];
    const float* log_kappa   = (const float*)d_in[3];

    int K = in_sizes[1];            // 64
    int D = in_sizes[2] / K;        // 256
    int N = in_sizes[0] / D;        // 262144
    (void)n_in; (void)out_size;

    float* out = (float*)d_out;
    float* llh = out;               // (N,)
    float* lp  = out + (size_t)N;   // (N, K)

    prep_fast<<<K_COMP, 128>>>(alpha_logit, mu_unnorm, log_kappa);

    cudaLaunchConfig_t cfg = {};
    cfg.gridDim  = dim3(N / 256, 1, 1);
    cfg.blockDim = dim3(256, 1, 1);
    cfg.dynamicSmemBytes = 0;
    cudaLaunchAttribute attrs[1];
    attrs[0].id = cudaLaunchAttributeProgrammaticStreamSerialization;
    attrs[0].val.programmaticStreamSerializationAllowed = 1;
    cfg.attrs = attrs;
    cfg.numAttrs = 1;
    cudaLaunchKernelEx(&cfg, vmf_main, x, mu_unnorm, llh, lp, N);
}